// round 15
// baseline (speedup 1.0000x reference)
#include <cuda_runtime.h>
#include <cuda_bf16.h>
#include <cstdint>

// ---------------------------------------------------------------------------
// Problem constants
// ---------------------------------------------------------------------------
#define NN 100000
#define EE 1600000
#define DT 768
#define DV 512
#define DE 128
#define NC 40

#define KT_TOTAL 1664   // 768 + 512 + 256 + 128  (concatenated weight K)
#define KOFF_T   0
#define KOFF_V   768
#define KOFF_M0  1280
#define KOFF_M1  1536

// ---------------------------------------------------------------------------
// Scratch (device globals — no allocation allowed)
// ---------------------------------------------------------------------------
__device__ float g_et[(size_t)NN * DE];
__device__ float g_ev[(size_t)NN * DE];
__device__ float g_t [(size_t)NN * DE];
__device__ float g_h [(size_t)NN * DE];
__device__ int   g_deg_in [NN];
__device__ int   g_deg_out[NN];
__device__ int   g_row    [NN];
__device__ int   g_cursor [NN];
__device__ int   g_bsum   [128];
__device__ float g_inv_in [NN];
__device__ float g_inv_out[NN];
__device__ int   g_csr_src[EE];
__device__ float g_csr_w  [EE];
// weights, transposed to [N=128][K] and split to bf16 hi/lo
__device__ __nv_bfloat16 g_WbH[(size_t)128 * KT_TOTAL];
__device__ __nv_bfloat16 g_WbL[(size_t)128 * KT_TOTAL];
// activations pre-split to bf16 hi/lo (GEMM A operands, cp.async-ready)
__device__ __nv_bfloat16 g_AtH[(size_t)NN * DT];
__device__ __nv_bfloat16 g_AtL[(size_t)NN * DT];
__device__ __nv_bfloat16 g_AvH[(size_t)NN * DV];
__device__ __nv_bfloat16 g_AvL[(size_t)NN * DV];
__device__ __nv_bfloat16 g_etH[(size_t)NN * DE];
__device__ __nv_bfloat16 g_etL[(size_t)NN * DE];
__device__ __nv_bfloat16 g_evH[(size_t)NN * DE];
__device__ __nv_bfloat16 g_evL[(size_t)NN * DE];
__device__ __nv_bfloat16 g_hH [(size_t)NN * DE];
__device__ __nv_bfloat16 g_hL [(size_t)NN * DE];

// ---------------------------------------------------------------------------
// PTX helpers (sm_80-era features only — compute_103 gates 'a'-suffix instrs)
// ---------------------------------------------------------------------------
__device__ __forceinline__ uint32_t smem_u32(const void* p) {
    uint32_t a;
    asm("{ .reg .u64 t; cvta.to.shared.u64 t, %1; cvt.u32.u64 %0, t; }" : "=r"(a) : "l"(p));
    return a;
}
__device__ __forceinline__ uint64_t gaddr(const void* p) {
    uint64_t a;
    asm("cvta.to.global.u64 %0, %1;" : "=l"(a) : "l"(p));
    return a;
}
#define CP16(dst, src, sz) \
    asm volatile("cp.async.cg.shared.global [%0], [%1], 16, %2;" :: "r"(dst), "l"(src), "r"(sz))
#define CP_COMMIT() asm volatile("cp.async.commit_group;" ::: "memory")
#define CP_WAIT0()  asm volatile("cp.async.wait_group 0;" ::: "memory")
#define CP_WAIT1()  asm volatile("cp.async.wait_group 1;" ::: "memory")

__device__ __forceinline__ void ldsm4(uint32_t* r, uint32_t addr) {
    asm volatile("ldmatrix.sync.aligned.m8n8.x4.shared.b16 {%0,%1,%2,%3}, [%4];"
        : "=r"(r[0]), "=r"(r[1]), "=r"(r[2]), "=r"(r[3]) : "r"(addr));
}
__device__ __forceinline__ void mma16816(float* d, const uint32_t* a, const uint32_t* b) {
    asm volatile("mma.sync.aligned.m16n8k16.row.col.f32.bf16.bf16.f32 "
        "{%0,%1,%2,%3}, {%4,%5,%6,%7}, {%8,%9}, {%0,%1,%2,%3};"
        : "+f"(d[0]), "+f"(d[1]), "+f"(d[2]), "+f"(d[3])
        : "r"(a[0]), "r"(a[1]), "r"(a[2]), "r"(a[3]), "r"(b[0]), "r"(b[1]));
}

__device__ __forceinline__ uint32_t pack_hi(float x, float y) {
    __nv_bfloat16 a = __float2bfloat16_rn(x), b = __float2bfloat16_rn(y);
    return ((uint32_t)__bfloat16_as_ushort(b) << 16) | __bfloat16_as_ushort(a);
}
__device__ __forceinline__ uint32_t pack_lo(float x, float y) {
    __nv_bfloat16 a = __float2bfloat16_rn(x), b = __float2bfloat16_rn(y);
    __nv_bfloat16 la = __float2bfloat16_rn(x - __bfloat162float(a));
    __nv_bfloat16 lb = __float2bfloat16_rn(y - __bfloat162float(b));
    return ((uint32_t)__bfloat16_as_ushort(lb) << 16) | __bfloat16_as_ushort(la);
}

// ---------------------------------------------------------------------------
// Activation preconversion: A [M*K] fp32 -> H/L bf16 (same layout)
// ---------------------------------------------------------------------------
__global__ void aconv_kernel(const float* __restrict__ A,
                             __nv_bfloat16* __restrict__ H,
                             __nv_bfloat16* __restrict__ L, long nq) {
    long i = (long)blockIdx.x * blockDim.x + threadIdx.x;
    if (i >= nq) return;
    float4 v = __ldg((const float4*)A + i);
    uint2 h = make_uint2(pack_hi(v.x, v.y), pack_hi(v.z, v.w));
    uint2 l = make_uint2(pack_lo(v.x, v.y), pack_lo(v.z, v.w));
    *((uint2*)H + i) = h;
    *((uint2*)L + i) = l;
}

// ---------------------------------------------------------------------------
// Weight preconversion (all 4 weights in one launch):
//   W[k][128] fp32 -> g_WbH/g_WbL [n=128][KT_TOTAL] bf16
// ---------------------------------------------------------------------------
__global__ void wconv_all(const float* __restrict__ Wt, const float* __restrict__ Wv,
                          const float* __restrict__ Wm0, const float* __restrict__ Wm1) {
    int i = blockIdx.x * blockDim.x + threadIdx.x;
    if (i >= KT_TOTAL * 128) return;
    int k = i >> 7, n = i & 127;
    float x;
    if      (k < 768)  x = Wt [(size_t)k * 128 + n];
    else if (k < 1280) x = Wv [(size_t)(k - 768) * 128 + n];
    else if (k < 1536) x = Wm0[(size_t)(k - 1280) * 128 + n];
    else               x = Wm1[(size_t)(k - 1536) * 128 + n];
    __nv_bfloat16 hi = __float2bfloat16_rn(x);
    __nv_bfloat16 lo = __float2bfloat16_rn(x - __bfloat162float(hi));
    size_t d = (size_t)n * KT_TOTAL + k;
    g_WbH[d] = hi;
    g_WbL[d] = lo;
}

// ---------------------------------------------------------------------------
// Degree / CSR kernels
// ---------------------------------------------------------------------------
__global__ void zero3_kernel(int n) {
    int i = blockIdx.x * blockDim.x + threadIdx.x;
    if (i < n) { g_deg_in[i] = 0; g_deg_out[i] = 0; g_cursor[i] = 0; }
}
__global__ void hist_kernel(const int* __restrict__ src, const int* __restrict__ dst, int e) {
    int i = blockIdx.x * blockDim.x + threadIdx.x;
    if (i < e) { atomicAdd(&g_deg_out[src[i]], 1); atomicAdd(&g_deg_in[dst[i]], 1); }
}
__global__ void inv_kernel(int n) {
    int i = blockIdx.x * blockDim.x + threadIdx.x;
    if (i < n) {
        int dout = g_deg_out[i]; if (dout < 1) dout = 1;
        int din  = g_deg_in [i]; if (din  < 1) din  = 1;
        g_inv_out[i] = rsqrtf((float)dout);
        g_inv_in [i] = rsqrtf((float)din);
    }
}
__global__ void scan_local(int n) {
    __shared__ int s[1024];
    int t = threadIdx.x;
    int gid = blockIdx.x * 1024 + t;
    int v = (gid < n) ? g_deg_in[gid] : 0;
    s[t] = v; __syncthreads();
    for (int off = 1; off < 1024; off <<= 1) {
        int x = (t >= off) ? s[t - off] : 0;
        __syncthreads(); s[t] += x; __syncthreads();
    }
    if (gid < n) g_row[gid] = s[t] - v;
    if (t == 1023) g_bsum[blockIdx.x] = s[1023];
}
__global__ void scan_bsums(int nb) {
    if (blockIdx.x == 0 && threadIdx.x == 0) {
        int run = 0;
        for (int i = 0; i < nb; i++) { int v = g_bsum[i]; g_bsum[i] = run; run += v; }
    }
}
__global__ void scan_add(int n) {
    int gid = blockIdx.x * blockDim.x + threadIdx.x;
    if (gid < n) g_row[gid] += g_bsum[gid >> 10];
}
__global__ void scatter_kernel(const int* __restrict__ src, const int* __restrict__ dst, int e) {
    int i = blockIdx.x * blockDim.x + threadIdx.x;
    if (i < e) {
        int s = src[i], d = dst[i];
        int pos = atomicAdd(&g_cursor[d], 1);
        int idx = g_row[d] + pos;
        g_csr_src[idx] = s;
        g_csr_w[idx]   = g_inv_out[s] * g_inv_in[d];
    }
}

// ---------------------------------------------------------------------------
// bf16 split GEMM, pure cp.async/ldmatrix/mma inner loop.
//   C[M x 128] = A[M x K] @ W[K x 128]   (A pre-split bf16 hi/lo in gmem)
// BK=32, 2 smem stages (80 KB) -> 2 CTAs/SM. 8 warps: (wm 0-3) x (wn 0-1).
// ---------------------------------------------------------------------------
#define BK2   32
#define ROWB2 80                      // bytes per 32-bf16 row (5 x 16B, odd -> conflict-free)
#define TILE2 (128 * ROWB2)           // 10240
#define O_AH  0
#define O_AL  (1 * TILE2)
#define O_BH  (2 * TILE2)
#define O_BL  (3 * TILE2)
#define STG2  (4 * TILE2)             // 40960
#define SMEM2 (2 * STG2)              // 81920

template <bool RELU, bool BIAS, bool WF32, bool WBF>
__global__ __launch_bounds__(256, 2)
void gemm_mma2(const __nv_bfloat16* __restrict__ A0h, const __nv_bfloat16* __restrict__ A0l,
               int K0,
               const __nv_bfloat16* __restrict__ A1h, const __nv_bfloat16* __restrict__ A1l,
               int K1,
               int koffW, const float* __restrict__ bias,
               float* __restrict__ Cf,
               __nv_bfloat16* __restrict__ CH, __nv_bfloat16* __restrict__ CL,
               int M) {
    extern __shared__ char smem[];
    const uint32_t sb = smem_u32(smem);

    const int tid  = threadIdx.x;
    const int lane = tid & 31;
    const int wid  = tid >> 5;
    const int wm   = wid & 3;
    const int wn   = wid >> 2;
    const int rowBase = blockIdx.x * 128;
    const int nc = (K0 + K1) >> 5;

    // cp.async mapping: 2 threads per row, 2 x 16B per thread per tile
    const int row = tid >> 1;
    const int j0  = (tid & 1) * 2;
    const int gr  = rowBase + row;
    const uint32_t szA = (gr < M) ? 16u : 0u;
    const int grc = (gr < M) ? gr : (M - 1);

    const uint64_t WbH = gaddr((const void*)g_WbH);
    const uint64_t WbL = gaddr((const void*)g_WbL);
    const uint64_t bRow = (uint64_t)((size_t)row * KT_TOTAL + koffW) * 2;

    auto issue = [&](int c, int s) {
        int kb = c * BK2;
        const __nv_bfloat16 *Ah, *Al; int K, kcol;
        if (kb < K0) { Ah = A0h; Al = A0l; K = K0; kcol = kb; }
        else         { Ah = A1h; Al = A1l; K = K1; kcol = kb - K0; }
        uint64_t sAh = gaddr(Ah) + (uint64_t)((size_t)grc * K + kcol) * 2;
        uint64_t sAl = gaddr(Al) + (uint64_t)((size_t)grc * K + kcol) * 2;
        uint64_t sBh = WbH + bRow + (uint64_t)kb * 2;
        uint64_t sBl = WbL + bRow + (uint64_t)kb * 2;
        uint32_t drow = sb + s * STG2 + row * ROWB2;
#pragma unroll
        for (int j = 0; j < 2; j++) {
            int u = (j0 + j) * 16;
            CP16(drow + O_AH + u, sAh + u, szA);
            CP16(drow + O_AL + u, sAl + u, szA);
            CP16(drow + O_BH + u, sBh + u, 16u);
            CP16(drow + O_BL + u, sBl + u, 16u);
        }
    };

    float acc[2][8][4];
#pragma unroll
    for (int f = 0; f < 2; f++)
#pragma unroll
        for (int nf = 0; nf < 8; nf++)
#pragma unroll
            for (int j = 0; j < 4; j++) acc[f][nf][j] = 0.f;

    auto compute = [&](int s) {
        uint32_t st = sb + s * STG2;
#pragma unroll
        for (int ks = 0; ks < 2; ks++) {
            uint32_t aH[2][4], aL[2][4];
#pragma unroll
            for (int f = 0; f < 2; f++) {
                uint32_t ra = st + O_AH
                    + (uint32_t)((wm * 32 + f * 16 + (lane & 15)) * ROWB2
                                 + (ks * 16 + (lane >> 4) * 8) * 2);
                ldsm4(aH[f], ra);
                ldsm4(aL[f], ra + (O_AL - O_AH));
            }
            uint32_t bH[4][4], bL[4][4];
            const int mi = lane >> 3;
#pragma unroll
            for (int np = 0; np < 4; np++) {
                uint32_t rb = st + O_BH
                    + (uint32_t)((wn * 64 + np * 16 + (mi >> 1) * 8 + (lane & 7)) * ROWB2
                                 + (ks * 16 + (mi & 1) * 8) * 2);
                ldsm4(bH[np], rb);
                ldsm4(bL[np], rb + (O_BL - O_BH));
            }
#pragma unroll
            for (int np = 0; np < 4; np++)
#pragma unroll
                for (int f = 0; f < 2; f++) {
                    mma16816(acc[f][2 * np],     aH[f], bH[np]);
                    mma16816(acc[f][2 * np + 1], aH[f], bH[np] + 2);
                    mma16816(acc[f][2 * np],     aH[f], bL[np]);
                    mma16816(acc[f][2 * np + 1], aH[f], bL[np] + 2);
                    mma16816(acc[f][2 * np],     aL[f], bH[np]);
                    mma16816(acc[f][2 * np + 1], aL[f], bH[np] + 2);
                }
        }
    };

    // prologue: 2 stages in flight
    issue(0, 0); CP_COMMIT();
    if (nc > 1) { issue(1, 1); CP_COMMIT(); }

    for (int c = 0; c < nc; c++) {
        if (c + 1 < nc) { CP_WAIT1(); } else { CP_WAIT0(); }
        __syncthreads();
        compute(c & 1);
        __syncthreads();
        if (c + 2 < nc) { issue(c + 2, c & 1); CP_COMMIT(); }
    }

    // epilogue
#pragma unroll
    for (int f = 0; f < 2; f++) {
#pragma unroll
        for (int nf = 0; nf < 8; nf++) {
            int n = wn * 64 + nf * 8 + (lane & 3) * 2;
            float b0 = 0.f, b1 = 0.f;
            if (BIAS) { b0 = __ldg(bias + n); b1 = __ldg(bias + n + 1); }
            int m0 = rowBase + wm * 32 + f * 16 + (lane >> 2);
            int m1 = m0 + 8;
            float v0 = acc[f][nf][0] + b0, v1 = acc[f][nf][1] + b1;
            float v2 = acc[f][nf][2] + b0, v3 = acc[f][nf][3] + b1;
            if (RELU) {
                v0 = fmaxf(v0, 0.f); v1 = fmaxf(v1, 0.f);
                v2 = fmaxf(v2, 0.f); v3 = fmaxf(v3, 0.f);
            }
            if (m0 < M) {
                if (WF32) *(float2*)(Cf + (size_t)m0 * 128 + n) = make_float2(v0, v1);
                if (WBF) {
                    *(uint32_t*)(CH + (size_t)m0 * 128 + n) = pack_hi(v0, v1);
                    *(uint32_t*)(CL + (size_t)m0 * 128 + n) = pack_lo(v0, v1);
                }
            }
            if (m1 < M) {
                if (WF32) *(float2*)(Cf + (size_t)m1 * 128 + n) = make_float2(v2, v3);
                if (WBF) {
                    *(uint32_t*)(CH + (size_t)m1 * 128 + n) = pack_hi(v2, v3);
                    *(uint32_t*)(CL + (size_t)m1 * 128 + n) = pack_lo(v2, v3);
                }
            }
        }
    }
}

// ---------------------------------------------------------------------------
// Edge aggregation. OUT=0: fp32 out; OUT=1: bf16 hi/lo out (for next GEMM).
// ---------------------------------------------------------------------------
template <int OUT>
__global__ void aggregate2(const float* __restrict__ t, const float* __restrict__ bias,
                           float* __restrict__ outf,
                           __nv_bfloat16* __restrict__ oh, __nv_bfloat16* __restrict__ ol,
                           int n) {
    int warp = (blockIdx.x * blockDim.x + threadIdx.x) >> 5;
    int lane = threadIdx.x & 31;
    if (warp >= n) return;
    int start = g_row[warp];
    int cnt   = g_deg_in[warp];
    const int c = lane * 4;
    float4 acc = make_float4(0.f, 0.f, 0.f, 0.f);
    int i = 0;
    for (; i + 1 < cnt; i += 2) {
        int   s0 = g_csr_src[start + i];
        float w0 = g_csr_w  [start + i];
        int   s1 = g_csr_src[start + i + 1];
        float w1 = g_csr_w  [start + i + 1];
        float4 v0 = *(const float4*)(t + (size_t)s0 * 128 + c);
        float4 v1 = *(const float4*)(t + (size_t)s1 * 128 + c);
        acc.x += w0 * v0.x; acc.y += w0 * v0.y; acc.z += w0 * v0.z; acc.w += w0 * v0.w;
        acc.x += w1 * v1.x; acc.y += w1 * v1.y; acc.z += w1 * v1.z; acc.w += w1 * v1.w;
    }
    for (; i < cnt; i++) {
        int   s = g_csr_src[start + i];
        float w = g_csr_w  [start + i];
        float4 v = *(const float4*)(t + (size_t)s * 128 + c);
        acc.x += w * v.x; acc.y += w * v.y; acc.z += w * v.z; acc.w += w * v.w;
    }
    float4 b = *(const float4*)(bias + c);
    acc.x += b.x; acc.y += b.y; acc.z += b.z; acc.w += b.w;
    if (OUT == 0) {
        *(float4*)(outf + (size_t)warp * 128 + c) = acc;
    } else {
        uint2 h = make_uint2(pack_hi(acc.x, acc.y), pack_hi(acc.z, acc.w));
        uint2 l = make_uint2(pack_lo(acc.x, acc.y), pack_lo(acc.z, acc.w));
        *(uint2*)(oh + (size_t)warp * 128 + c) = h;
        *(uint2*)(ol + (size_t)warp * 128 + c) = l;
    }
}

// ---------------------------------------------------------------------------
// Heads (unchanged)
// ---------------------------------------------------------------------------
__global__ void heads_kernel(const float* __restrict__ et, const float* __restrict__ ev,
                             const float* __restrict__ h,
                             const float* __restrict__ Wc, const float* __restrict__ bc,
                             const float* __restrict__ Wt, const float* __restrict__ bt,
                             const float* __restrict__ Wv, const float* __restrict__ bv,
                             float* __restrict__ out, int n) {
    extern __shared__ float sw[];
    float* sWc = sw;
    float* sWt = sw + 5120;
    float* sWv = sw + 10240;
    for (int i = threadIdx.x; i < 5120; i += blockDim.x) {
        sWc[i] = Wc[i]; sWt[i] = Wt[i]; sWv[i] = Wv[i];
    }
    __syncthreads();

    int warp   = (blockIdx.x * blockDim.x + threadIdx.x) >> 5;
    int lane   = threadIdx.x & 31;
    int nwarps = (gridDim.x * blockDim.x) >> 5;
    bool s2 = lane < 8;
    int col1 = lane, col2 = 32 + lane;
    size_t MO = (size_t)n * 40;

    for (int node = warp; node < n; node += nwarps) {
        const float* xt = et + (size_t)node * 128;
        const float* xv = ev + (size_t)node * 128;
        const float* xh = h  + (size_t)node * 128;
        float c0 = 0.f, c1 = 0.f, t0 = 0.f, t1 = 0.f, v0 = 0.f, v1 = 0.f;
#pragma unroll 4
        for (int k = 0; k < 128; k++) {
            float a = xh[k], b = xt[k], c = xv[k];
            c0 += a * sWc[k * 40 + col1];
            t0 += b * sWt[k * 40 + col1];
            v0 += c * sWv[k * 40 + col1];
            if (s2) {
                c1 += a * sWc[k * 40 + col2];
                t1 += b * sWt[k * 40 + col2];
                v1 += c * sWv[k * 40 + col2];
            }
        }
        c0 += bc[col1]; t0 += bt[col1]; v0 += bv[col1];
        float f0 = (c0 + t0 + v0) * (1.f / 3.f);
        size_t base = (size_t)node * 40;
        out[base + col1]          = f0;
        out[MO + base + col1]     = c0;
        out[2 * MO + base + col1] = t0;
        out[3 * MO + base + col1] = v0;
        if (s2) {
            c1 += bc[col2]; t1 += bt[col2]; v1 += bv[col2];
            float f1 = (c1 + t1 + v1) * (1.f / 3.f);
            out[base + col2]          = f1;
            out[MO + base + col2]     = c1;
            out[2 * MO + base + col2] = t1;
            out[3 * MO + base + col2] = v1;
        }
    }
}

// ---------------------------------------------------------------------------
// Launch.  Order puts gemm_text at launch index 3 (ncu capture slot).
// ---------------------------------------------------------------------------
extern "C" void kernel_launch(void* const* d_in, const int* in_sizes, int n_in,
                              void* d_out, int out_size) {
    const float* text = (const float*)d_in[0];
    const float* vis  = (const float*)d_in[1];
    const int* esrc   = (const int*)d_in[2];
    const int* edst   = (const int*)d_in[3];
    const float* W_t  = (const float*)d_in[4];
    const float* b_t  = (const float*)d_in[5];
    const float* W_v  = (const float*)d_in[6];
    const float* b_v  = (const float*)d_in[7];
    const float* W_mp0 = (const float*)d_in[8];
    const float* b_mp0 = (const float*)d_in[9];
    const float* W_mp1 = (const float*)d_in[10];
    const float* b_mp1 = (const float*)d_in[11];
    const float* W_c  = (const float*)d_in[12];
    const float* b_c  = (const float*)d_in[13];
    const float* W_ut = (const float*)d_in[14];
    const float* b_ut = (const float*)d_in[15];
    const float* W_uv = (const float*)d_in[16];
    const float* b_uv = (const float*)d_in[17];
    float* out = (float*)d_out;

    int n = in_sizes[0] / DT;
    int e = in_sizes[2];

    float *p_et, *p_ev, *p_t, *p_h;
    __nv_bfloat16 *p_AtH, *p_AtL, *p_AvH, *p_AvL;
    __nv_bfloat16 *p_etH, *p_etL, *p_evH, *p_evL, *p_hH, *p_hL;
    cudaGetSymbolAddress((void**)&p_et, g_et);
    cudaGetSymbolAddress((void**)&p_ev, g_ev);
    cudaGetSymbolAddress((void**)&p_t,  g_t);
    cudaGetSymbolAddress((void**)&p_h,  g_h);
    cudaGetSymbolAddress((void**)&p_AtH, g_AtH);
    cudaGetSymbolAddress((void**)&p_AtL, g_AtL);
    cudaGetSymbolAddress((void**)&p_AvH, g_AvH);
    cudaGetSymbolAddress((void**)&p_AvL, g_AvL);
    cudaGetSymbolAddress((void**)&p_etH, g_etH);
    cudaGetSymbolAddress((void**)&p_etL, g_etL);
    cudaGetSymbolAddress((void**)&p_evH, g_evH);
    cudaGetSymbolAddress((void**)&p_evL, g_evL);
    cudaGetSymbolAddress((void**)&p_hH,  g_hH);
    cudaGetSymbolAddress((void**)&p_hL,  g_hL);

    int nb_n = (n + 255) / 256;
    int nb_e = (e + 255) / 256;
    int nb_scan = (n + 1023) / 1024;
    int gm = (n + 127) / 128;

    cudaFuncSetAttribute(gemm_mma2<true, true, true, true>,
                         cudaFuncAttributeMaxDynamicSharedMemorySize, SMEM2);
    cudaFuncSetAttribute(gemm_mma2<false, false, true, false>,
                         cudaFuncAttributeMaxDynamicSharedMemorySize, SMEM2);

    // 0,1: activation preconversion
    long nq_t = (long)n * DT / 4;
    long nq_v = (long)n * DV / 4;
    aconv_kernel<<<(int)((nq_t + 255) / 256), 256>>>(text, p_AtH, p_AtL, nq_t);
    aconv_kernel<<<(int)((nq_v + 255) / 256), 256>>>(vis,  p_AvH, p_AvL, nq_v);
    // 2: weight preconversion
    wconv_all<<<(KT_TOTAL * 128 + 255) / 256, 256>>>(W_t, W_v, W_mp0, W_mp1);

    // 3: text encoder GEMM (ncu capture slot)
    gemm_mma2<true, true, true, true><<<gm, 256, SMEM2>>>(
        p_AtH, p_AtL, DT, nullptr, nullptr, 0, KOFF_T, b_t,
        p_et, p_etH, p_etL, n);
    // 4: vis encoder GEMM
    gemm_mma2<true, true, true, true><<<gm, 256, SMEM2>>>(
        p_AvH, p_AvL, DV, nullptr, nullptr, 0, KOFF_V, b_v,
        p_ev, p_evH, p_evL, n);

    // 5-11: graph prep
    zero3_kernel<<<nb_n, 256>>>(n);
    hist_kernel<<<nb_e, 256>>>(esrc, edst, e);
    inv_kernel<<<nb_n, 256>>>(n);
    scan_local<<<nb_scan, 1024>>>(n);
    scan_bsums<<<1, 32>>>(nb_scan);
    scan_add<<<nb_n, 256>>>(n);
    scatter_kernel<<<nb_e, 256>>>(esrc, edst, e);

    // GCN layer 0: concat(et, ev) @ W_mp0 (K=256, two segments), aggregate
    gemm_mma2<false, false, true, false><<<gm, 256, SMEM2>>>(
        p_etH, p_etL, DE, p_evH, p_evL, DE, KOFF_M0, nullptr,
        p_t, nullptr, nullptr, n);
    aggregate2<1><<<(n + 7) / 8, 256>>>(p_t, b_mp0, nullptr, p_hH, p_hL, n);

    // GCN layer 1
    gemm_mma2<false, false, true, false><<<gm, 256, SMEM2>>>(
        p_hH, p_hL, DE, nullptr, nullptr, 0, KOFF_M1, nullptr,
        p_t, nullptr, nullptr, n);
    aggregate2<0><<<(n + 7) / 8, 256>>>(p_t, b_mp1, p_h, nullptr, nullptr, n);

    // heads
    size_t smem_heads = 3 * 5120 * sizeof(float);
    cudaFuncSetAttribute(heads_kernel, cudaFuncAttributeMaxDynamicSharedMemorySize,
                         (int)smem_heads);
    heads_kernel<<<1184, 256, smem_heads>>>(p_et, p_ev, p_h,
                                            W_c, b_c, W_ut, b_ut, W_uv, b_uv,
                                            out, n);
}

// round 16
// speedup vs baseline: 1.0944x; 1.0944x over previous
#include <cuda_runtime.h>
#include <cuda_bf16.h>
#include <cstdint>

// ---------------------------------------------------------------------------
// Problem constants
// ---------------------------------------------------------------------------
#define NN 100000
#define EE 1600000
#define DT 768
#define DV 512
#define DE 128
#define NC 40

#define KT_TOTAL 1664   // 768 + 512 + 256 + 128
#define KOFF_T   0
#define KOFF_V   768
#define KOFF_M0  1280
#define KOFF_M1  1536

// ---------------------------------------------------------------------------
// Scratch (device globals — no allocation allowed)
// ---------------------------------------------------------------------------
__device__ float g_et[(size_t)NN * DE];
__device__ float g_ev[(size_t)NN * DE];
__device__ float g_t [(size_t)NN * DE];
__device__ float g_h [(size_t)NN * DE];
__device__ int   g_deg_in [NN];
__device__ int   g_deg_out[NN];
__device__ int   g_row    [NN];
__device__ int   g_cursor [NN];
__device__ int   g_bsum   [128];
__device__ float g_inv_in [NN];
__device__ float g_inv_out[NN];
__device__ int   g_csr_src[EE];
__device__ float g_csr_w  [EE];
// weights, transposed to [N=128][K] and split to bf16 hi/lo
__device__ __nv_bfloat16 g_WbH[(size_t)128 * KT_TOTAL];
__device__ __nv_bfloat16 g_WbL[(size_t)128 * KT_TOTAL];
// intermediate activations in bf16 hi/lo (produced by epilogues)
__device__ __nv_bfloat16 g_etH[(size_t)NN * DE];
__device__ __nv_bfloat16 g_etL[(size_t)NN * DE];
__device__ __nv_bfloat16 g_evH[(size_t)NN * DE];
__device__ __nv_bfloat16 g_evL[(size_t)NN * DE];
__device__ __nv_bfloat16 g_hH [(size_t)NN * DE];
__device__ __nv_bfloat16 g_hL [(size_t)NN * DE];

// ---------------------------------------------------------------------------
// PTX helpers (sm_80-era only — compute_103 gates 'a'-suffix instructions)
// ---------------------------------------------------------------------------
__device__ __forceinline__ uint32_t smem_u32(const void* p) {
    uint32_t a;
    asm("{ .reg .u64 t; cvta.to.shared.u64 t, %1; cvt.u32.u64 %0, t; }" : "=r"(a) : "l"(p));
    return a;
}
__device__ __forceinline__ uint64_t gaddr(const void* p) {
    uint64_t a;
    asm("cvta.to.global.u64 %0, %1;" : "=l"(a) : "l"(p));
    return a;
}
#define CP16(dst, src, sz) \
    asm volatile("cp.async.cg.shared.global [%0], [%1], 16, %2;" :: "r"(dst), "l"(src), "r"(sz))
#define CP_COMMIT() asm volatile("cp.async.commit_group;" ::: "memory")
#define CP_WAIT0()  asm volatile("cp.async.wait_group 0;" ::: "memory")
#define CP_WAIT1()  asm volatile("cp.async.wait_group 1;" ::: "memory")

__device__ __forceinline__ void ldsm4(uint32_t* r, uint32_t addr) {
    asm volatile("ldmatrix.sync.aligned.m8n8.x4.shared.b16 {%0,%1,%2,%3}, [%4];"
        : "=r"(r[0]), "=r"(r[1]), "=r"(r[2]), "=r"(r[3]) : "r"(addr));
}
__device__ __forceinline__ void mma16816(float* d, const uint32_t* a, const uint32_t* b) {
    asm volatile("mma.sync.aligned.m16n8k16.row.col.f32.bf16.bf16.f32 "
        "{%0,%1,%2,%3}, {%4,%5,%6,%7}, {%8,%9}, {%0,%1,%2,%3};"
        : "+f"(d[0]), "+f"(d[1]), "+f"(d[2]), "+f"(d[3])
        : "r"(a[0]), "r"(a[1]), "r"(a[2]), "r"(a[3]), "r"(b[0]), "r"(b[1]));
}

__device__ __forceinline__ uint32_t pack_hi(float x, float y) {
    __nv_bfloat16 a = __float2bfloat16_rn(x), b = __float2bfloat16_rn(y);
    return ((uint32_t)__bfloat16_as_ushort(b) << 16) | __bfloat16_as_ushort(a);
}
__device__ __forceinline__ uint32_t pack_lo(float x, float y) {
    __nv_bfloat16 a = __float2bfloat16_rn(x), b = __float2bfloat16_rn(y);
    __nv_bfloat16 la = __float2bfloat16_rn(x - __bfloat162float(a));
    __nv_bfloat16 lb = __float2bfloat16_rn(y - __bfloat162float(b));
    return ((uint32_t)__bfloat16_as_ushort(lb) << 16) | __bfloat16_as_ushort(la);
}

// ---------------------------------------------------------------------------
// Weight preconversion (all 4 weights in one launch):
//   W[k][128] fp32 -> g_WbH/g_WbL [n=128][KT_TOTAL] bf16
// ---------------------------------------------------------------------------
__global__ void wconv_all(const float* __restrict__ Wt, const float* __restrict__ Wv,
                          const float* __restrict__ Wm0, const float* __restrict__ Wm1) {
    int i = blockIdx.x * blockDim.x + threadIdx.x;
    if (i >= KT_TOTAL * 128) return;
    int k = i >> 7, n = i & 127;
    float x;
    if      (k < 768)  x = Wt [(size_t)k * 128 + n];
    else if (k < 1280) x = Wv [(size_t)(k - 768) * 128 + n];
    else if (k < 1536) x = Wm0[(size_t)(k - 1280) * 128 + n];
    else               x = Wm1[(size_t)(k - 1536) * 128 + n];
    __nv_bfloat16 hi = __float2bfloat16_rn(x);
    __nv_bfloat16 lo = __float2bfloat16_rn(x - __bfloat162float(hi));
    size_t d = (size_t)n * KT_TOTAL + k;
    g_WbH[d] = hi;
    g_WbL[d] = lo;
}

// ---------------------------------------------------------------------------
// Degree / CSR kernels
// ---------------------------------------------------------------------------
__global__ void zero3_kernel(int n) {
    int i = blockIdx.x * blockDim.x + threadIdx.x;
    if (i < n) { g_deg_in[i] = 0; g_deg_out[i] = 0; g_cursor[i] = 0; }
}
__global__ void hist_kernel(const int* __restrict__ src, const int* __restrict__ dst, int e) {
    int i = blockIdx.x * blockDim.x + threadIdx.x;
    if (i < e) { atomicAdd(&g_deg_out[src[i]], 1); atomicAdd(&g_deg_in[dst[i]], 1); }
}
__global__ void inv_kernel(int n) {
    int i = blockIdx.x * blockDim.x + threadIdx.x;
    if (i < n) {
        int dout = g_deg_out[i]; if (dout < 1) dout = 1;
        int din  = g_deg_in [i]; if (din  < 1) din  = 1;
        g_inv_out[i] = rsqrtf((float)dout);
        g_inv_in [i] = rsqrtf((float)din);
    }
}
__global__ void scan_local(int n) {
    __shared__ int s[1024];
    int t = threadIdx.x;
    int gid = blockIdx.x * 1024 + t;
    int v = (gid < n) ? g_deg_in[gid] : 0;
    s[t] = v; __syncthreads();
    for (int off = 1; off < 1024; off <<= 1) {
        int x = (t >= off) ? s[t - off] : 0;
        __syncthreads(); s[t] += x; __syncthreads();
    }
    if (gid < n) g_row[gid] = s[t] - v;
    if (t == 1023) g_bsum[blockIdx.x] = s[1023];
}
__global__ void scan_bsums(int nb) {
    if (blockIdx.x == 0 && threadIdx.x == 0) {
        int run = 0;
        for (int i = 0; i < nb; i++) { int v = g_bsum[i]; g_bsum[i] = run; run += v; }
    }
}
__global__ void scan_add(int n) {
    int gid = blockIdx.x * blockDim.x + threadIdx.x;
    if (gid < n) g_row[gid] += g_bsum[gid >> 10];
}
__global__ void scatter_kernel(const int* __restrict__ src, const int* __restrict__ dst, int e) {
    int i = blockIdx.x * blockDim.x + threadIdx.x;
    if (i < e) {
        int s = src[i], d = dst[i];
        int pos = atomicAdd(&g_cursor[d], 1);
        int idx = g_row[d] + pos;
        g_csr_src[idx] = s;
        g_csr_w[idx]   = g_inv_out[s] * g_inv_in[d];
    }
}

// ---------------------------------------------------------------------------
// bf16 split GEMM, M-tile 256, BK=32, 3 smem stages, 1 sync per chunk.
//   C[M x 128] = A[M x K] @ W[K x 128]
// AF32=1: A is fp32 in gmem (LDG prefetch -> convert -> STS).
// AF32=0: A pre-split bf16 hi/lo, staged via cp.async (optionally 2 segments).
// 8 warps: wm = wid>>1 (64 rows), wn = wid&1 (64 cols).
// ---------------------------------------------------------------------------
#define BK3   32
#define RB3   80                      // bytes per 32-bf16 row (5 x 16B)
#define O3_AH 0
#define O3_AL 20480                   // 256*80
#define O3_BH 40960
#define O3_BL 51200                   // + 128*80
#define STG3  61440
#define SMEM3 (3 * STG3)              // 184320

template <bool AF32, bool RELU, bool BIAS, bool WBF>
__global__ __launch_bounds__(256, 1)
void gemm3(const void* __restrict__ A0a, const void* __restrict__ A0b, int K0,
           const __nv_bfloat16* __restrict__ A1h, const __nv_bfloat16* __restrict__ A1l,
           int K1,
           int koffW, const float* __restrict__ bias,
           float* __restrict__ Cf,
           __nv_bfloat16* __restrict__ CH, __nv_bfloat16* __restrict__ CL,
           int M) {
    extern __shared__ char smem[];
    const uint32_t sb = smem_u32(smem);

    const int tid  = threadIdx.x;
    const int lane = tid & 31;
    const int wid  = tid >> 5;
    const int wm   = wid >> 1;         // 0..3, 64 rows each
    const int wn   = wid & 1;          // 0..1, 64 cols each
    const int rowBase = blockIdx.x * 256;
    const int nc = (K0 + K1) >> 5;

    // A mapping: 1 thread per row (256 rows)
    const int arow = tid;
    const int gr   = rowBase + arow;
    const bool okA = gr < M;
    const int grc  = okA ? gr : (M - 1);
    const uint32_t szA = okA ? 16u : 0u;

    // B mapping: 2 threads per row, 2 x 16B each (per hi/lo)
    const int brow = tid >> 1;
    const int j0   = (tid & 1) * 2;
    const uint64_t WbH = gaddr((const void*)g_WbH);
    const uint64_t WbL = gaddr((const void*)g_WbL);
    const uint64_t bRow = (uint64_t)((size_t)brow * KT_TOTAL + koffW) * 2;

    auto issueB = [&](int c, int s) {
        uint64_t kb2 = (uint64_t)(c * BK3) * 2;
        uint64_t sH = WbH + bRow + kb2;
        uint64_t sL = WbL + bRow + kb2;
        uint32_t drow = sb + s * STG3 + brow * RB3;
#pragma unroll
        for (int j = 0; j < 2; j++) {
            int u = (j0 + j) * 16;
            CP16(drow + O3_BH + u, sH + u, 16u);
            CP16(drow + O3_BL + u, sL + u, 16u);
        }
    };

    auto issueA_bf = [&](int c, int s) {
        int kb = c * BK3;
        const __nv_bfloat16 *Ah, *Al; int K, kcol;
        if (kb < K0) { Ah = (const __nv_bfloat16*)A0a; Al = (const __nv_bfloat16*)A0b;
                       K = K0; kcol = kb; }
        else         { Ah = A1h; Al = A1l; K = K1; kcol = kb - K0; }
        uint64_t sH = gaddr(Ah) + (uint64_t)((size_t)grc * K + kcol) * 2;
        uint64_t sL = gaddr(Al) + (uint64_t)((size_t)grc * K + kcol) * 2;
        uint32_t drow = sb + s * STG3 + arow * RB3;
#pragma unroll
        for (int u = 0; u < 4; u++) {
            CP16(drow + O3_AH + u * 16, sH + u * 16, szA);
            CP16(drow + O3_AL + u * 16, sL + u * 16, szA);
        }
    };

    auto ldgA = [&](int c, float4* av) {
        const float* rp = (const float*)A0a + (size_t)grc * K0 + c * BK3;
#pragma unroll
        for (int j = 0; j < 8; j++)
            av[j] = okA ? __ldg((const float4*)rp + j) : make_float4(0.f, 0.f, 0.f, 0.f);
    };
    auto stsA = [&](int s, const float4* av) {
        char* st = smem + s * STG3 + arow * RB3;
#pragma unroll
        for (int j = 0; j < 4; j++) {
            float4 a = av[2 * j], b = av[2 * j + 1];
            uint4 h = make_uint4(pack_hi(a.x, a.y), pack_hi(a.z, a.w),
                                 pack_hi(b.x, b.y), pack_hi(b.z, b.w));
            uint4 l = make_uint4(pack_lo(a.x, a.y), pack_lo(a.z, a.w),
                                 pack_lo(b.x, b.y), pack_lo(b.z, b.w));
            *(uint4*)(st + O3_AH + j * 16) = h;
            *(uint4*)(st + O3_AL + j * 16) = l;
        }
    };

    float acc[4][8][4];
#pragma unroll
    for (int f = 0; f < 4; f++)
#pragma unroll
        for (int nf = 0; nf < 8; nf++)
#pragma unroll
            for (int j = 0; j < 4; j++) acc[f][nf][j] = 0.f;

    auto compute = [&](int s) {
        uint32_t st = sb + s * STG3;
#pragma unroll
        for (int ks = 0; ks < 2; ks++) {
            uint32_t aH[4][4], aL[4][4];
#pragma unroll
            for (int f = 0; f < 4; f++) {
                uint32_t ra = st + O3_AH
                    + (uint32_t)((wm * 64 + f * 16 + (lane & 15)) * RB3
                                 + (ks * 16 + (lane >> 4) * 8) * 2);
                ldsm4(aH[f], ra);
                ldsm4(aL[f], ra + (O3_AL - O3_AH));
            }
            const int mi = lane >> 3;
            uint32_t bH[4][4], bL[4][4];
#pragma unroll
            for (int np = 0; np < 4; np++) {
                uint32_t rb = st + O3_BH
                    + (uint32_t)((wn * 64 + np * 16 + (mi >> 1) * 8 + (lane & 7)) * RB3
                                 + (ks * 16 + (mi & 1) * 8) * 2);
                ldsm4(bH[np], rb);
                ldsm4(bL[np], rb + (O3_BL - O3_BH));
            }
#pragma unroll
            for (int np = 0; np < 4; np++)
#pragma unroll
                for (int f = 0; f < 4; f++) {
                    mma16816(acc[f][2 * np],     aH[f], bH[np]);
                    mma16816(acc[f][2 * np + 1], aH[f], bH[np] + 2);
                    mma16816(acc[f][2 * np],     aH[f], bL[np]);
                    mma16816(acc[f][2 * np + 1], aH[f], bL[np] + 2);
                    mma16816(acc[f][2 * np],     aL[f], bH[np]);
                    mma16816(acc[f][2 * np + 1], aL[f], bH[np] + 2);
                }
        }
    };

    // ---- prologue: chunks 0,1 into stages 0,1 ----
    if (AF32) {
        float4 av0[8];
        ldgA(0, av0); stsA(0, av0);
        issueB(0, 0); CP_COMMIT();
        ldgA(1, av0); stsA(1, av0);
        issueB(1, 1); CP_COMMIT();
    } else {
        issueA_bf(0, 0); issueB(0, 0); CP_COMMIT();
        issueA_bf(1, 1); issueB(1, 1); CP_COMMIT();
    }

    // ---- mainloop: 1 sync per chunk; refill stage (c+2)%3 after compute ----
    float4 av[8];
    for (int c = 0; c < nc; c++) {
        if (c + 1 < nc) { CP_WAIT1(); } else { CP_WAIT0(); }
        __syncthreads();
        bool more = (c + 2) < nc;
        if (AF32 && more) ldgA(c + 2, av);
        int s = c % 3;
        compute(s);
        if (more) {
            int sn = (c + 2) % 3;
            if (AF32) stsA(sn, av);
            else      issueA_bf(c + 2, sn);
            issueB(c + 2, sn);
            CP_COMMIT();
        }
    }

    // ---- epilogue ----
#pragma unroll
    for (int f = 0; f < 4; f++) {
#pragma unroll
        for (int nf = 0; nf < 8; nf++) {
            int n = wn * 64 + nf * 8 + (lane & 3) * 2;
            float b0 = 0.f, b1 = 0.f;
            if (BIAS) { b0 = __ldg(bias + n); b1 = __ldg(bias + n + 1); }
            int m0 = rowBase + wm * 64 + f * 16 + (lane >> 2);
            int m1 = m0 + 8;
            float v0 = acc[f][nf][0] + b0, v1 = acc[f][nf][1] + b1;
            float v2 = acc[f][nf][2] + b0, v3 = acc[f][nf][3] + b1;
            if (RELU) {
                v0 = fmaxf(v0, 0.f); v1 = fmaxf(v1, 0.f);
                v2 = fmaxf(v2, 0.f); v3 = fmaxf(v3, 0.f);
            }
            if (m0 < M) {
                *(float2*)(Cf + (size_t)m0 * 128 + n) = make_float2(v0, v1);
                if (WBF) {
                    *(uint32_t*)(CH + (size_t)m0 * 128 + n) = pack_hi(v0, v1);
                    *(uint32_t*)(CL + (size_t)m0 * 128 + n) = pack_lo(v0, v1);
                }
            }
            if (m1 < M) {
                *(float2*)(Cf + (size_t)m1 * 128 + n) = make_float2(v2, v3);
                if (WBF) {
                    *(uint32_t*)(CH + (size_t)m1 * 128 + n) = pack_hi(v2, v3);
                    *(uint32_t*)(CL + (size_t)m1 * 128 + n) = pack_lo(v2, v3);
                }
            }
        }
    }
}

// ---------------------------------------------------------------------------
// Edge aggregation. OUT=0: fp32 out; OUT=1: bf16 hi/lo out (for next GEMM).
// ---------------------------------------------------------------------------
template <int OUT>
__global__ void aggregate2(const float* __restrict__ t, const float* __restrict__ bias,
                           float* __restrict__ outf,
                           __nv_bfloat16* __restrict__ oh, __nv_bfloat16* __restrict__ ol,
                           int n) {
    int warp = (blockIdx.x * blockDim.x + threadIdx.x) >> 5;
    int lane = threadIdx.x & 31;
    if (warp >= n) return;
    int start = g_row[warp];
    int cnt   = g_deg_in[warp];
    const int c = lane * 4;
    float4 acc = make_float4(0.f, 0.f, 0.f, 0.f);
    int i = 0;
    for (; i + 1 < cnt; i += 2) {
        int   s0 = g_csr_src[start + i];
        float w0 = g_csr_w  [start + i];
        int   s1 = g_csr_src[start + i + 1];
        float w1 = g_csr_w  [start + i + 1];
        float4 v0 = *(const float4*)(t + (size_t)s0 * 128 + c);
        float4 v1 = *(const float4*)(t + (size_t)s1 * 128 + c);
        acc.x += w0 * v0.x; acc.y += w0 * v0.y; acc.z += w0 * v0.z; acc.w += w0 * v0.w;
        acc.x += w1 * v1.x; acc.y += w1 * v1.y; acc.z += w1 * v1.z; acc.w += w1 * v1.w;
    }
    for (; i < cnt; i++) {
        int   s = g_csr_src[start + i];
        float w = g_csr_w  [start + i];
        float4 v = *(const float4*)(t + (size_t)s * 128 + c);
        acc.x += w * v.x; acc.y += w * v.y; acc.z += w * v.z; acc.w += w * v.w;
    }
    float4 b = *(const float4*)(bias + c);
    acc.x += b.x; acc.y += b.y; acc.z += b.z; acc.w += b.w;
    if (OUT == 0) {
        *(float4*)(outf + (size_t)warp * 128 + c) = acc;
    } else {
        uint2 h = make_uint2(pack_hi(acc.x, acc.y), pack_hi(acc.z, acc.w));
        uint2 l = make_uint2(pack_lo(acc.x, acc.y), pack_lo(acc.z, acc.w));
        *(uint2*)(oh + (size_t)warp * 128 + c) = h;
        *(uint2*)(ol + (size_t)warp * 128 + c) = l;
    }
}

// ---------------------------------------------------------------------------
// Heads
// ---------------------------------------------------------------------------
__global__ void heads_kernel(const float* __restrict__ et, const float* __restrict__ ev,
                             const float* __restrict__ h,
                             const float* __restrict__ Wc, const float* __restrict__ bc,
                             const float* __restrict__ Wt, const float* __restrict__ bt,
                             const float* __restrict__ Wv, const float* __restrict__ bv,
                             float* __restrict__ out, int n) {
    extern __shared__ float sw[];
    float* sWc = sw;
    float* sWt = sw + 5120;
    float* sWv = sw + 10240;
    for (int i = threadIdx.x; i < 5120; i += blockDim.x) {
        sWc[i] = Wc[i]; sWt[i] = Wt[i]; sWv[i] = Wv[i];
    }
    __syncthreads();

    int warp   = (blockIdx.x * blockDim.x + threadIdx.x) >> 5;
    int lane   = threadIdx.x & 31;
    int nwarps = (gridDim.x * blockDim.x) >> 5;
    bool s2 = lane < 8;
    int col1 = lane, col2 = 32 + lane;
    size_t MO = (size_t)n * 40;

    for (int node = warp; node < n; node += nwarps) {
        const float* xt = et + (size_t)node * 128;
        const float* xv = ev + (size_t)node * 128;
        const float* xh = h  + (size_t)node * 128;
        float c0 = 0.f, c1 = 0.f, t0 = 0.f, t1 = 0.f, v0 = 0.f, v1 = 0.f;
#pragma unroll 4
        for (int k = 0; k < 128; k++) {
            float a = xh[k], b = xt[k], c = xv[k];
            c0 += a * sWc[k * 40 + col1];
            t0 += b * sWt[k * 40 + col1];
            v0 += c * sWv[k * 40 + col1];
            if (s2) {
                c1 += a * sWc[k * 40 + col2];
                t1 += b * sWt[k * 40 + col2];
                v1 += c * sWv[k * 40 + col2];
            }
        }
        c0 += bc[col1]; t0 += bt[col1]; v0 += bv[col1];
        float f0 = (c0 + t0 + v0) * (1.f / 3.f);
        size_t base = (size_t)node * 40;
        out[base + col1]          = f0;
        out[MO + base + col1]     = c0;
        out[2 * MO + base + col1] = t0;
        out[3 * MO + base + col1] = v0;
        if (s2) {
            c1 += bc[col2]; t1 += bt[col2]; v1 += bv[col2];
            float f1 = (c1 + t1 + v1) * (1.f / 3.f);
            out[base + col2]          = f1;
            out[MO + base + col2]     = c1;
            out[2 * MO + base + col2] = t1;
            out[3 * MO + base + col2] = v1;
        }
    }
}

// ---------------------------------------------------------------------------
// Launch.  gemm_text at launch index 3 (ncu capture slot).
// ---------------------------------------------------------------------------
extern "C" void kernel_launch(void* const* d_in, const int* in_sizes, int n_in,
                              void* d_out, int out_size) {
    const float* text = (const float*)d_in[0];
    const float* vis  = (const float*)d_in[1];
    const int* esrc   = (const int*)d_in[2];
    const int* edst   = (const int*)d_in[3];
    const float* W_t  = (const float*)d_in[4];
    const float* b_t  = (const float*)d_in[5];
    const float* W_v  = (const float*)d_in[6];
    const float* b_v  = (const float*)d_in[7];
    const float* W_mp0 = (const float*)d_in[8];
    const float* b_mp0 = (const float*)d_in[9];
    const float* W_mp1 = (const float*)d_in[10];
    const float* b_mp1 = (const float*)d_in[11];
    const float* W_c  = (const float*)d_in[12];
    const float* b_c  = (const float*)d_in[13];
    const float* W_ut = (const float*)d_in[14];
    const float* b_ut = (const float*)d_in[15];
    const float* W_uv = (const float*)d_in[16];
    const float* b_uv = (const float*)d_in[17];
    float* out = (float*)d_out;

    int n = in_sizes[0] / DT;
    int e = in_sizes[2];

    float *p_et, *p_ev, *p_t, *p_h;
    __nv_bfloat16 *p_etH, *p_etL, *p_evH, *p_evL, *p_hH, *p_hL;
    cudaGetSymbolAddress((void**)&p_et, g_et);
    cudaGetSymbolAddress((void**)&p_ev, g_ev);
    cudaGetSymbolAddress((void**)&p_t,  g_t);
    cudaGetSymbolAddress((void**)&p_h,  g_h);
    cudaGetSymbolAddress((void**)&p_etH, g_etH);
    cudaGetSymbolAddress((void**)&p_etL, g_etL);
    cudaGetSymbolAddress((void**)&p_evH, g_evH);
    cudaGetSymbolAddress((void**)&p_evL, g_evL);
    cudaGetSymbolAddress((void**)&p_hH,  g_hH);
    cudaGetSymbolAddress((void**)&p_hL,  g_hL);

    int nb_n = (n + 255) / 256;
    int nb_e = (e + 255) / 256;
    int nb_scan = (n + 1023) / 1024;
    int gm = (n + 255) / 256;

    cudaFuncSetAttribute(gemm3<true, true, true, true>,
                         cudaFuncAttributeMaxDynamicSharedMemorySize, SMEM3);
    cudaFuncSetAttribute(gemm3<false, false, false, false>,
                         cudaFuncAttributeMaxDynamicSharedMemorySize, SMEM3);

    // 0: weights; 1,2: graph prep openers
    wconv_all<<<(KT_TOTAL * 128 + 255) / 256, 256>>>(W_t, W_v, W_mp0, W_mp1);
    zero3_kernel<<<nb_n, 256>>>(n);
    hist_kernel<<<nb_e, 256>>>(esrc, edst, e);

    // 3: text encoder GEMM (ncu capture slot), fp32 A direct
    gemm3<true, true, true, true><<<gm, 256, SMEM3>>>(
        text, nullptr, DT, nullptr, nullptr, 0, KOFF_T, b_t,
        p_et, p_etH, p_etL, n);
    // 4: vis encoder GEMM
    gemm3<true, true, true, true><<<gm, 256, SMEM3>>>(
        vis, nullptr, DV, nullptr, nullptr, 0, KOFF_V, b_v,
        p_ev, p_evH, p_evL, n);

    // 5-9: graph prep
    inv_kernel<<<nb_n, 256>>>(n);
    scan_local<<<nb_scan, 1024>>>(n);
    scan_bsums<<<1, 32>>>(nb_scan);
    scan_add<<<nb_n, 256>>>(n);
    scatter_kernel<<<nb_e, 256>>>(esrc, edst, e);

    // GCN layer 0: concat(et, ev) @ W_mp0 (K=256, 2 segments), aggregate
    gemm3<false, false, false, false><<<gm, 256, SMEM3>>>(
        p_etH, p_etL, DE, p_evH, p_evL, DE, KOFF_M0, nullptr,
        p_t, nullptr, nullptr, n);
    aggregate2<1><<<(n + 7) / 8, 256>>>(p_t, b_mp0, nullptr, p_hH, p_hL, n);

    // GCN layer 1
    gemm3<false, false, false, false><<<gm, 256, SMEM3>>>(
        p_hH, p_hL, DE, nullptr, nullptr, 0, KOFF_M1, nullptr,
        p_t, nullptr, nullptr, n);
    aggregate2<0><<<(n + 7) / 8, 256>>>(p_t, b_mp1, p_h, nullptr, nullptr, n);

    // heads
    size_t smem_heads = 3 * 5120 * sizeof(float);
    cudaFuncSetAttribute(heads_kernel, cudaFuncAttributeMaxDynamicSharedMemorySize,
                         (int)smem_heads);
    heads_kernel<<<1184, 256, smem_heads>>>(p_et, p_ev, p_h,
                                            W_c, b_c, W_ut, b_ut, W_uv, b_uv,
                                            out, n);
}

// round 17
// speedup vs baseline: 1.7901x; 1.6356x over previous
#include <cuda_runtime.h>
#include <cuda_bf16.h>
#include <cstdint>

// ---------------------------------------------------------------------------
// Problem constants
// ---------------------------------------------------------------------------
#define NN 100000
#define EE 1600000
#define DT 768
#define DV 512
#define DE 128
#define NC 40

#define KT_TOTAL 1664   // 768 + 512 + 256 + 128
#define KOFF_T   0
#define KOFF_V   768
#define KOFF_M0  1280
#define KOFF_M1  1536

// ---------------------------------------------------------------------------
// Scratch (device globals — no allocation allowed)
// ---------------------------------------------------------------------------
__device__ float g_t [(size_t)NN * DE];       // mp GEMM f32 output (agg input)
__device__ int   g_deg_in [NN];
__device__ int   g_deg_out[NN];
__device__ int   g_row    [NN];
__device__ int   g_cursor [NN];
__device__ int   g_bsum   [128];
__device__ float g_inv_in [NN];
__device__ float g_inv_out[NN];
__device__ int   g_csr_src[EE];
__device__ float g_csr_w  [EE];
// weights, transposed to [N=128][K] and split to bf16 hi/lo
__device__ __nv_bfloat16 g_WbH[(size_t)128 * KT_TOTAL];
__device__ __nv_bfloat16 g_WbL[(size_t)128 * KT_TOTAL];
// head weights: [3][48][128] bf16 hi/lo ([n][k], rows 40-47 zero)
__device__ __nv_bfloat16 g_WHH[(size_t)3 * 48 * 128];
__device__ __nv_bfloat16 g_WHL[(size_t)3 * 48 * 128];
// activations bf16 hi/lo
__device__ __nv_bfloat16 g_etH[(size_t)NN * DE];
__device__ __nv_bfloat16 g_etL[(size_t)NN * DE];
__device__ __nv_bfloat16 g_evH[(size_t)NN * DE];
__device__ __nv_bfloat16 g_evL[(size_t)NN * DE];
__device__ __nv_bfloat16 g_hH [(size_t)NN * DE];   // agg0 out
__device__ __nv_bfloat16 g_hL [(size_t)NN * DE];
__device__ __nv_bfloat16 g_h2H[(size_t)NN * DE];   // agg1 out
__device__ __nv_bfloat16 g_h2L[(size_t)NN * DE];

// ---------------------------------------------------------------------------
// PTX helpers (sm_80-era only — compute_103 gates 'a'-suffix instructions)
// ---------------------------------------------------------------------------
__device__ __forceinline__ uint32_t smem_u32(const void* p) {
    uint32_t a;
    asm("{ .reg .u64 t; cvta.to.shared.u64 t, %1; cvt.u32.u64 %0, t; }" : "=r"(a) : "l"(p));
    return a;
}
__device__ __forceinline__ uint64_t gaddr(const void* p) {
    uint64_t a;
    asm("cvta.to.global.u64 %0, %1;" : "=l"(a) : "l"(p));
    return a;
}
#define CP16(dst, src, sz) \
    asm volatile("cp.async.cg.shared.global [%0], [%1], 16, %2;" :: "r"(dst), "l"(src), "r"(sz))
#define CP_COMMIT() asm volatile("cp.async.commit_group;" ::: "memory")
#define CP_WAIT0()  asm volatile("cp.async.wait_group 0;" ::: "memory")
#define CP_WAIT1()  asm volatile("cp.async.wait_group 1;" ::: "memory")

__device__ __forceinline__ void ldsm4(uint32_t* r, uint32_t addr) {
    asm volatile("ldmatrix.sync.aligned.m8n8.x4.shared.b16 {%0,%1,%2,%3}, [%4];"
        : "=r"(r[0]), "=r"(r[1]), "=r"(r[2]), "=r"(r[3]) : "r"(addr));
}
__device__ __forceinline__ void mma16816(float* d, const uint32_t* a, const uint32_t* b) {
    asm volatile("mma.sync.aligned.m16n8k16.row.col.f32.bf16.bf16.f32 "
        "{%0,%1,%2,%3}, {%4,%5,%6,%7}, {%8,%9}, {%0,%1,%2,%3};"
        : "+f"(d[0]), "+f"(d[1]), "+f"(d[2]), "+f"(d[3])
        : "r"(a[0]), "r"(a[1]), "r"(a[2]), "r"(a[3]), "r"(b[0]), "r"(b[1]));
}

__device__ __forceinline__ uint32_t pack_hi(float x, float y) {
    __nv_bfloat16 a = __float2bfloat16_rn(x), b = __float2bfloat16_rn(y);
    return ((uint32_t)__bfloat16_as_ushort(b) << 16) | __bfloat16_as_ushort(a);
}
__device__ __forceinline__ uint32_t pack_lo(float x, float y) {
    __nv_bfloat16 a = __float2bfloat16_rn(x), b = __float2bfloat16_rn(y);
    __nv_bfloat16 la = __float2bfloat16_rn(x - __bfloat162float(a));
    __nv_bfloat16 lb = __float2bfloat16_rn(y - __bfloat162float(b));
    return ((uint32_t)__bfloat16_as_ushort(lb) << 16) | __bfloat16_as_ushort(la);
}

// ---------------------------------------------------------------------------
// Weight preconversion
// ---------------------------------------------------------------------------
__global__ void wconv_all(const float* __restrict__ Wt, const float* __restrict__ Wv,
                          const float* __restrict__ Wm0, const float* __restrict__ Wm1) {
    int i = blockIdx.x * blockDim.x + threadIdx.x;
    if (i >= KT_TOTAL * 128) return;
    int k = i >> 7, n = i & 127;
    float x;
    if      (k < 768)  x = Wt [(size_t)k * 128 + n];
    else if (k < 1280) x = Wv [(size_t)(k - 768) * 128 + n];
    else if (k < 1536) x = Wm0[(size_t)(k - 1280) * 128 + n];
    else               x = Wm1[(size_t)(k - 1536) * 128 + n];
    __nv_bfloat16 hi = __float2bfloat16_rn(x);
    __nv_bfloat16 lo = __float2bfloat16_rn(x - __bfloat162float(hi));
    size_t d = (size_t)n * KT_TOTAL + k;
    g_WbH[d] = hi;
    g_WbL[d] = lo;
}

// head weights: W[128][40] f32 -> [h][n=48][k=128] bf16 hi/lo (n>=40 zero)
__global__ void whconv(const float* __restrict__ Wc, const float* __restrict__ Wt,
                       const float* __restrict__ Wv) {
    int i = blockIdx.x * blockDim.x + threadIdx.x;
    if (i >= 3 * 48 * 128) return;
    int h = i / (48 * 128);
    int r = i % (48 * 128);
    int n = r >> 7, k = r & 127;
    const float* W = (h == 0) ? Wc : (h == 1) ? Wt : Wv;
    float x = (n < 40) ? W[(size_t)k * 40 + n] : 0.f;
    __nv_bfloat16 hi = __float2bfloat16_rn(x);
    __nv_bfloat16 lo = __float2bfloat16_rn(x - __bfloat162float(hi));
    g_WHH[i] = hi;
    g_WHL[i] = lo;
}

// ---------------------------------------------------------------------------
// Degree / CSR kernels
// ---------------------------------------------------------------------------
__global__ void zero3_kernel(int n) {
    int i = blockIdx.x * blockDim.x + threadIdx.x;
    if (i < n) { g_deg_in[i] = 0; g_deg_out[i] = 0; g_cursor[i] = 0; }
}
__global__ void hist_kernel(const int* __restrict__ src, const int* __restrict__ dst, int e) {
    int i = blockIdx.x * blockDim.x + threadIdx.x;
    if (i < e) { atomicAdd(&g_deg_out[src[i]], 1); atomicAdd(&g_deg_in[dst[i]], 1); }
}
__global__ void inv_kernel(int n) {
    int i = blockIdx.x * blockDim.x + threadIdx.x;
    if (i < n) {
        int dout = g_deg_out[i]; if (dout < 1) dout = 1;
        int din  = g_deg_in [i]; if (din  < 1) din  = 1;
        g_inv_out[i] = rsqrtf((float)dout);
        g_inv_in [i] = rsqrtf((float)din);
    }
}
__global__ void scan_local(int n) {
    __shared__ int s[1024];
    int t = threadIdx.x;
    int gid = blockIdx.x * 1024 + t;
    int v = (gid < n) ? g_deg_in[gid] : 0;
    s[t] = v; __syncthreads();
    for (int off = 1; off < 1024; off <<= 1) {
        int x = (t >= off) ? s[t - off] : 0;
        __syncthreads(); s[t] += x; __syncthreads();
    }
    if (gid < n) g_row[gid] = s[t] - v;
    if (t == 1023) g_bsum[blockIdx.x] = s[1023];
}
__global__ void scan_bsums(int nb) {
    if (blockIdx.x == 0 && threadIdx.x == 0) {
        int run = 0;
        for (int i = 0; i < nb; i++) { int v = g_bsum[i]; g_bsum[i] = run; run += v; }
    }
}
__global__ void scan_add(int n) {
    int gid = blockIdx.x * blockDim.x + threadIdx.x;
    if (gid < n) g_row[gid] += g_bsum[gid >> 10];
}
__global__ void scatter_kernel(const int* __restrict__ src, const int* __restrict__ dst, int e) {
    int i = blockIdx.x * blockDim.x + threadIdx.x;
    if (i < e) {
        int s = src[i], d = dst[i];
        int pos = atomicAdd(&g_cursor[d], 1);
        int idx = g_row[d] + pos;
        g_csr_src[idx] = s;
        g_csr_w[idx]   = g_inv_out[s] * g_inv_in[d];
    }
}

// ---------------------------------------------------------------------------
// Main GEMM: C[M x 128] = A[M x K] @ W[K x 128]
// Tile 128x128, BK=32, interleaved hi/lo rows (144B), 3 stages, 1 sync/chunk,
// 2 CTAs/SM. 8 warps: wm = wid&3 (32 rows), wn = wid>>2 (64 cols).
// AF32=1: A fp32 (LDG->convert->STS). AF32=0: A bf16 hi/lo via cp.async.
// ---------------------------------------------------------------------------
#define RB    144                    // row bytes: 64 hi + 64 lo + 16 pad
#define TILEB (128 * RB)             // 18432
#define OFF_B TILEB
#define STG   (2 * TILEB)            // 36864
#define SMEMG (3 * STG)              // 110592

template <bool AF32, bool RELU, bool BIAS, bool WF32, bool WBF>
__global__ __launch_bounds__(256, 2)
void gemm3(const void* __restrict__ A0a, const void* __restrict__ A0b, int K0,
           const __nv_bfloat16* __restrict__ A1h, const __nv_bfloat16* __restrict__ A1l,
           int K1,
           int koffW, const float* __restrict__ bias,
           float* __restrict__ Cf,
           __nv_bfloat16* __restrict__ CH, __nv_bfloat16* __restrict__ CL,
           int M) {
    extern __shared__ char smem[];
    const uint32_t sb = smem_u32(smem);

    const int tid  = threadIdx.x;
    const int lane = tid & 31;
    const int wid  = tid >> 5;
    const int wm   = wid & 3;
    const int wn   = wid >> 2;
    const int rowBase = blockIdx.x * 128;
    const int nc = (K0 + K1) >> 5;

    // load mapping: 2 threads per row (A and B both 128 rows)
    const int arow = tid >> 1;
    const int j0   = (tid & 1) * 2;         // chunk pair base (0 or 2)
    const int gr   = rowBase + arow;
    const bool okA = gr < M;
    const int grc  = okA ? gr : (M - 1);
    const uint32_t szA = okA ? 16u : 0u;

    const uint64_t WbH = gaddr((const void*)g_WbH);
    const uint64_t WbL = gaddr((const void*)g_WbL);
    const uint64_t bRow = (uint64_t)((size_t)arow * KT_TOTAL + koffW) * 2;

    auto issueB = [&](int c, uint32_t st) {
        uint64_t k2 = (uint64_t)(c * 32 + j0 * 8) * 2;
        uint64_t sH = WbH + bRow + k2;
        uint64_t sL = WbL + bRow + k2;
        uint32_t d = st + OFF_B + arow * RB + j0 * 16;
        CP16(d,          sH,      16u);
        CP16(d + 16,     sH + 16, 16u);
        CP16(d + 64,     sL,      16u);
        CP16(d + 80,     sL + 16, 16u);
    };

    auto issueA_bf = [&](int c, uint32_t st) {
        int kb = c * 32;
        const __nv_bfloat16 *Ah, *Al; int K, kcol;
        if (kb < K0) { Ah = (const __nv_bfloat16*)A0a; Al = (const __nv_bfloat16*)A0b;
                       K = K0; kcol = kb; }
        else         { Ah = A1h; Al = A1l; K = K1; kcol = kb - K0; }
        uint64_t off = (uint64_t)((size_t)grc * K + kcol + j0 * 8) * 2;
        uint64_t sH = gaddr(Ah) + off;
        uint64_t sL = gaddr(Al) + off;
        uint32_t d = st + arow * RB + j0 * 16;
        CP16(d,        sH,      szA);
        CP16(d + 16,   sH + 16, szA);
        CP16(d + 64,   sL,      szA);
        CP16(d + 80,   sL + 16, szA);
    };

    auto ldgA = [&](int c, float4* av) {
        const float* rp = (const float*)A0a + (size_t)grc * K0 + c * 32 + j0 * 8;
#pragma unroll
        for (int j = 0; j < 4; j++)
            av[j] = okA ? __ldg((const float4*)rp + j) : make_float4(0.f, 0.f, 0.f, 0.f);
    };
    auto stsA = [&](uint32_t st, const float4* av) {
        uint32_t d = st + arow * RB + j0 * 16;
        uint4 h0 = make_uint4(pack_hi(av[0].x, av[0].y), pack_hi(av[0].z, av[0].w),
                              pack_hi(av[1].x, av[1].y), pack_hi(av[1].z, av[1].w));
        uint4 h1 = make_uint4(pack_hi(av[2].x, av[2].y), pack_hi(av[2].z, av[2].w),
                              pack_hi(av[3].x, av[3].y), pack_hi(av[3].z, av[3].w));
        uint4 l0 = make_uint4(pack_lo(av[0].x, av[0].y), pack_lo(av[0].z, av[0].w),
                              pack_lo(av[1].x, av[1].y), pack_lo(av[1].z, av[1].w));
        uint4 l1 = make_uint4(pack_lo(av[2].x, av[2].y), pack_lo(av[2].z, av[2].w),
                              pack_lo(av[3].x, av[3].y), pack_lo(av[3].z, av[3].w));
        *(uint4*)(smem + (d - sb))        = h0;
        *(uint4*)(smem + (d - sb) + 16)   = h1;
        *(uint4*)(smem + (d - sb) + 64)   = l0;
        *(uint4*)(smem + (d - sb) + 80)   = l1;
    };

    float acc[2][8][4];
#pragma unroll
    for (int f = 0; f < 2; f++)
#pragma unroll
        for (int nf = 0; nf < 8; nf++)
#pragma unroll
            for (int j = 0; j < 4; j++) acc[f][nf][j] = 0.f;

    auto compute = [&](uint32_t st) {
#pragma unroll
        for (int ks = 0; ks < 2; ks++) {
            uint32_t aH[2][4], aL[2][4];
#pragma unroll
            for (int f = 0; f < 2; f++) {
                uint32_t ra = st + (wm * 32 + f * 16 + (lane & 15)) * RB
                            + ks * 32 + (lane >> 4) * 16;
                ldsm4(aH[f], ra);
                ldsm4(aL[f], ra + 64);
            }
            const int mi = lane >> 3;
            uint32_t bH[4][4], bL[4][4];
#pragma unroll
            for (int np = 0; np < 4; np++) {
                uint32_t rb = st + OFF_B
                            + (wn * 64 + np * 16 + (mi >> 1) * 8 + (lane & 7)) * RB
                            + ks * 32 + (mi & 1) * 16;
                ldsm4(bH[np], rb);
                ldsm4(bL[np], rb + 64);
            }
#pragma unroll
            for (int np = 0; np < 4; np++)
#pragma unroll
                for (int f = 0; f < 2; f++) {
                    mma16816(acc[f][2 * np],     aH[f], bH[np]);
                    mma16816(acc[f][2 * np + 1], aH[f], bH[np] + 2);
                    mma16816(acc[f][2 * np],     aH[f], bL[np]);
                    mma16816(acc[f][2 * np + 1], aH[f], bL[np] + 2);
                    mma16816(acc[f][2 * np],     aL[f], bH[np]);
                    mma16816(acc[f][2 * np + 1], aL[f], bH[np] + 2);
                }
        }
    };

    uint32_t s0 = sb, s1 = sb + STG, s2 = sb + 2 * STG;

    // prologue: chunks 0,1 -> stages s0,s1
    if (AF32) {
        float4 av0[4];
        ldgA(0, av0); stsA(s0, av0);
        issueB(0, s0); CP_COMMIT();
        ldgA(1, av0); stsA(s1, av0);
        issueB(1, s1); CP_COMMIT();
    } else {
        issueA_bf(0, s0); issueB(0, s0); CP_COMMIT();
        issueA_bf(1, s1); issueB(1, s1); CP_COMMIT();
    }

    float4 av[4];
    for (int c = 0; c < nc; c++) {
        if (c + 1 < nc) { CP_WAIT1(); } else { CP_WAIT0(); }
        __syncthreads();
        bool more = (c + 2) < nc;
        if (AF32 && more) ldgA(c + 2, av);
        compute(s0);
        if (more) {
            if (AF32) stsA(s2, av);
            else      issueA_bf(c + 2, s2);
            issueB(c + 2, s2);
            CP_COMMIT();
        }
        uint32_t t = s0; s0 = s1; s1 = s2; s2 = t;
    }

    // epilogue
#pragma unroll
    for (int f = 0; f < 2; f++) {
#pragma unroll
        for (int nf = 0; nf < 8; nf++) {
            int n = wn * 64 + nf * 8 + (lane & 3) * 2;
            float b0 = 0.f, b1 = 0.f;
            if (BIAS) { b0 = __ldg(bias + n); b1 = __ldg(bias + n + 1); }
            int m0 = rowBase + wm * 32 + f * 16 + (lane >> 2);
            int m1 = m0 + 8;
            float v0 = acc[f][nf][0] + b0, v1 = acc[f][nf][1] + b1;
            float v2 = acc[f][nf][2] + b0, v3 = acc[f][nf][3] + b1;
            if (RELU) {
                v0 = fmaxf(v0, 0.f); v1 = fmaxf(v1, 0.f);
                v2 = fmaxf(v2, 0.f); v3 = fmaxf(v3, 0.f);
            }
            if (m0 < M) {
                if (WF32) *(float2*)(Cf + (size_t)m0 * 128 + n) = make_float2(v0, v1);
                if (WBF) {
                    *(uint32_t*)(CH + (size_t)m0 * 128 + n) = pack_hi(v0, v1);
                    *(uint32_t*)(CL + (size_t)m0 * 128 + n) = pack_lo(v0, v1);
                }
            }
            if (m1 < M) {
                if (WF32) *(float2*)(Cf + (size_t)m1 * 128 + n) = make_float2(v2, v3);
                if (WBF) {
                    *(uint32_t*)(CH + (size_t)m1 * 128 + n) = pack_hi(v2, v3);
                    *(uint32_t*)(CL + (size_t)m1 * 128 + n) = pack_lo(v2, v3);
                }
            }
        }
    }
}

// ---------------------------------------------------------------------------
// Heads GEMM: out[M x 40] = A[M x 128] @ W^T[128 x 40] + bias
// A bf16 hi/lo; W = g_WHH/g_WHL head slice [48][128]. M-tile 256, 8 warps
// (m32 each), N=48 frags (40 valid). B fully smem-resident; A one cp.async volley.
// ---------------------------------------------------------------------------
#define HRB   528                    // 256B hi + 256B lo + 16 pad
#define H_OB  (256 * HRB)            // A tile = 135168
#define SMEMH (H_OB + 48 * HRB)      // +25344 = 160512

__global__ __launch_bounds__(256, 1)
void gemm_heads(const __nv_bfloat16* __restrict__ Ah, const __nv_bfloat16* __restrict__ Al,
                int head, const float* __restrict__ bias,
                float* __restrict__ outp, int M) {
    extern __shared__ char smem[];
    const uint32_t sb = smem_u32(smem);
    const int tid  = threadIdx.x;
    const int lane = tid & 31;
    const int wid  = tid >> 5;
    const int rowBase = blockIdx.x * 256;

    // A: one row per thread, 16 hi chunks + 16 lo chunks
    {
        int gr = rowBase + tid;
        uint32_t sz = (gr < M) ? 16u : 0u;
        int grc = (gr < M) ? gr : (M - 1);
        uint64_t sH = gaddr(Ah) + (uint64_t)grc * 256;   // 128 bf16 = 256B
        uint64_t sL = gaddr(Al) + (uint64_t)grc * 256;
        uint32_t d = sb + tid * HRB;
#pragma unroll
        for (int u = 0; u < 16; u++) {
            CP16(d + u * 16,       sH + u * 16, sz);
            CP16(d + 256 + u * 16, sL + u * 16, sz);
        }
    }
    // B: 48 rows x 32 chunks = 1536 chunks over threads 0..191 (8 each)
    if (tid < 192) {
        int row = tid >> 2, p = tid & 3;
        uint64_t sH = gaddr((const void*)g_WHH) + ((uint64_t)head * 48 + row) * 256;
        uint64_t sL = gaddr((const void*)g_WHL) + ((uint64_t)head * 48 + row) * 256;
        uint32_t d = sb + H_OB + row * HRB;
#pragma unroll
        for (int j = 0; j < 4; j++) {
            int ch = p * 4 + j;
            CP16(d + ch * 16,       sH + ch * 16, 16u);
            CP16(d + 256 + ch * 16, sL + ch * 16, 16u);
        }
    }
    CP_COMMIT();
    CP_WAIT0();
    __syncthreads();

    float acc[2][6][4];
#pragma unroll
    for (int f = 0; f < 2; f++)
#pragma unroll
        for (int nf = 0; nf < 6; nf++)
#pragma unroll
            for (int j = 0; j < 4; j++) acc[f][nf][j] = 0.f;

    const int mi = lane >> 3;
#pragma unroll
    for (int ks = 0; ks < 8; ks++) {
        uint32_t aH[2][4], aL[2][4];
#pragma unroll
        for (int f = 0; f < 2; f++) {
            uint32_t ra = sb + (wid * 32 + f * 16 + (lane & 15)) * HRB
                        + ks * 32 + (lane >> 4) * 16;
            ldsm4(aH[f], ra);
            ldsm4(aL[f], ra + 256);
        }
#pragma unroll
        for (int np = 0; np < 3; np++) {
            uint32_t bH[4], bL[4];
            uint32_t rb = sb + H_OB + (np * 16 + (mi >> 1) * 8 + (lane & 7)) * HRB
                        + ks * 32 + (mi & 1) * 16;
            ldsm4(bH, rb);
            ldsm4(bL, rb + 256);
#pragma unroll
            for (int f = 0; f < 2; f++) {
                mma16816(acc[f][2 * np],     aH[f], bH);
                mma16816(acc[f][2 * np + 1], aH[f], bH + 2);
                mma16816(acc[f][2 * np],     aH[f], bL);
                mma16816(acc[f][2 * np + 1], aH[f], bL + 2);
                mma16816(acc[f][2 * np],     aL[f], bH);
                mma16816(acc[f][2 * np + 1], aL[f], bH + 2);
            }
        }
    }

    // epilogue: write n<40 cols
#pragma unroll
    for (int f = 0; f < 2; f++) {
#pragma unroll
        for (int nf = 0; nf < 6; nf++) {
            int n = nf * 8 + (lane & 3) * 2;
            if (n >= 40) continue;
            float b0 = __ldg(bias + n), b1 = __ldg(bias + n + 1);
            int m0 = rowBase + wid * 32 + f * 16 + (lane >> 2);
            int m1 = m0 + 8;
            if (m0 < M)
                *(float2*)(outp + (size_t)m0 * 40 + n)
                    = make_float2(acc[f][nf][0] + b0, acc[f][nf][1] + b1);
            if (m1 < M)
                *(float2*)(outp + (size_t)m1 * 40 + n)
                    = make_float2(acc[f][nf][2] + b0, acc[f][nf][3] + b1);
        }
    }
}

// final = (C + Ut + Uv) / 3   over n*40 contiguous floats
__global__ void avg_kernel(float* __restrict__ out, long m4) {
    long i = (long)blockIdx.x * blockDim.x + threadIdx.x;
    if (i >= m4) return;
    const float4* c = (const float4*)(out + 4 * m4) + i;   // m4 = quarter of MO... see launch
    const float4* t = (const float4*)(out + 8 * m4) + i;
    const float4* v = (const float4*)(out + 12 * m4) + i;
    float4 a = *c, b = *t, d = *v;
    float4 r;
    r.x = (a.x + b.x + d.x) * (1.f / 3.f);
    r.y = (a.y + b.y + d.y) * (1.f / 3.f);
    r.z = (a.z + b.z + d.z) * (1.f / 3.f);
    r.w = (a.w + b.w + d.w) * (1.f / 3.f);
    *((float4*)out + i) = r;
}

// ---------------------------------------------------------------------------
// Edge aggregation -> bf16 hi/lo (+bias)
// ---------------------------------------------------------------------------
__global__ void aggregate2(const float* __restrict__ t, const float* __restrict__ bias,
                           __nv_bfloat16* __restrict__ oh, __nv_bfloat16* __restrict__ ol,
                           int n) {
    int warp = (blockIdx.x * blockDim.x + threadIdx.x) >> 5;
    int lane = threadIdx.x & 31;
    if (warp >= n) return;
    int start = g_row[warp];
    int cnt   = g_deg_in[warp];
    const int c = lane * 4;
    float4 acc = make_float4(0.f, 0.f, 0.f, 0.f);
    int i = 0;
    for (; i + 1 < cnt; i += 2) {
        int   s0 = g_csr_src[start + i];
        float w0 = g_csr_w  [start + i];
        int   s1 = g_csr_src[start + i + 1];
        float w1 = g_csr_w  [start + i + 1];
        float4 v0 = *(const float4*)(t + (size_t)s0 * 128 + c);
        float4 v1 = *(const float4*)(t + (size_t)s1 * 128 + c);
        acc.x += w0 * v0.x; acc.y += w0 * v0.y; acc.z += w0 * v0.z; acc.w += w0 * v0.w;
        acc.x += w1 * v1.x; acc.y += w1 * v1.y; acc.z += w1 * v1.z; acc.w += w1 * v1.w;
    }
    for (; i < cnt; i++) {
        int   s = g_csr_src[start + i];
        float w = g_csr_w  [start + i];
        float4 v = *(const float4*)(t + (size_t)s * 128 + c);
        acc.x += w * v.x; acc.y += w * v.y; acc.z += w * v.z; acc.w += w * v.w;
    }
    float4 b = *(const float4*)(bias + c);
    acc.x += b.x; acc.y += b.y; acc.z += b.z; acc.w += b.w;
    uint2 h = make_uint2(pack_hi(acc.x, acc.y), pack_hi(acc.z, acc.w));
    uint2 l = make_uint2(pack_lo(acc.x, acc.y), pack_lo(acc.z, acc.w));
    *(uint2*)(oh + (size_t)warp * 128 + c) = h;
    *(uint2*)(ol + (size_t)warp * 128 + c) = l;
}

// ---------------------------------------------------------------------------
// Launch.  gemm_text at index 3 (ncu capture slot).
// ---------------------------------------------------------------------------
extern "C" void kernel_launch(void* const* d_in, const int* in_sizes, int n_in,
                              void* d_out, int out_size) {
    const float* text = (const float*)d_in[0];
    const float* vis  = (const float*)d_in[1];
    const int* esrc   = (const int*)d_in[2];
    const int* edst   = (const int*)d_in[3];
    const float* W_t  = (const float*)d_in[4];
    const float* b_t  = (const float*)d_in[5];
    const float* W_v  = (const float*)d_in[6];
    const float* b_v  = (const float*)d_in[7];
    const float* W_mp0 = (const float*)d_in[8];
    const float* b_mp0 = (const float*)d_in[9];
    const float* W_mp1 = (const float*)d_in[10];
    const float* b_mp1 = (const float*)d_in[11];
    const float* W_c  = (const float*)d_in[12];
    const float* b_c  = (const float*)d_in[13];
    const float* W_ut = (const float*)d_in[14];
    const float* b_ut = (const float*)d_in[15];
    const float* W_uv = (const float*)d_in[16];
    const float* b_uv = (const float*)d_in[17];
    float* out = (float*)d_out;

    int n = in_sizes[0] / DT;
    int e = in_sizes[2];

    float* p_t;
    __nv_bfloat16 *p_etH, *p_etL, *p_evH, *p_evL, *p_hH, *p_hL, *p_h2H, *p_h2L;
    cudaGetSymbolAddress((void**)&p_t,  g_t);
    cudaGetSymbolAddress((void**)&p_etH, g_etH);
    cudaGetSymbolAddress((void**)&p_etL, g_etL);
    cudaGetSymbolAddress((void**)&p_evH, g_evH);
    cudaGetSymbolAddress((void**)&p_evL, g_evL);
    cudaGetSymbolAddress((void**)&p_hH,  g_hH);
    cudaGetSymbolAddress((void**)&p_hL,  g_hL);
    cudaGetSymbolAddress((void**)&p_h2H, g_h2H);
    cudaGetSymbolAddress((void**)&p_h2L, g_h2L);

    int nb_n = (n + 255) / 256;
    int nb_e = (e + 255) / 256;
    int nb_scan = (n + 1023) / 1024;
    int gm  = (n + 127) / 128;
    int gmh = (n + 255) / 256;

    cudaFuncSetAttribute(gemm3<true, true, true, false, true>,
                         cudaFuncAttributeMaxDynamicSharedMemorySize, SMEMG);
    cudaFuncSetAttribute(gemm3<false, false, false, true, false>,
                         cudaFuncAttributeMaxDynamicSharedMemorySize, SMEMG);
    cudaFuncSetAttribute(gemm_heads,
                         cudaFuncAttributeMaxDynamicSharedMemorySize, SMEMH);

    // 0-2
    wconv_all<<<(KT_TOTAL * 128 + 255) / 256, 256>>>(W_t, W_v, W_mp0, W_mp1);
    zero3_kernel<<<nb_n, 256>>>(n);
    hist_kernel<<<nb_e, 256>>>(esrc, edst, e);

    // 3: text encoder (ncu slot), fp32 A
    gemm3<true, true, true, false, true><<<gm, 256, SMEMG>>>(
        text, nullptr, DT, nullptr, nullptr, 0, KOFF_T, b_t,
        nullptr, p_etH, p_etL, n);
    // 4: vis encoder
    gemm3<true, true, true, false, true><<<gm, 256, SMEMG>>>(
        vis, nullptr, DV, nullptr, nullptr, 0, KOFF_V, b_v,
        nullptr, p_evH, p_evL, n);

    // 5-10: head weights + graph prep
    whconv<<<(3 * 48 * 128 + 255) / 256, 256>>>(W_c, W_ut, W_uv);
    inv_kernel<<<nb_n, 256>>>(n);
    scan_local<<<nb_scan, 1024>>>(n);
    scan_bsums<<<1, 32>>>(nb_scan);
    scan_add<<<nb_n, 256>>>(n);
    scatter_kernel<<<nb_e, 256>>>(esrc, edst, e);

    // GCN layer 0: concat(et, ev) @ W_mp0 (K=256, 2 segments) -> f32, aggregate
    gemm3<false, false, false, true, false><<<gm, 256, SMEMG>>>(
        p_etH, p_etL, DE, p_evH, p_evL, DE, KOFF_M0, nullptr,
        p_t, nullptr, nullptr, n);
    aggregate2<<<(n + 7) / 8, 256>>>(p_t, b_mp0, p_hH, p_hL, n);

    // GCN layer 1
    gemm3<false, false, false, true, false><<<gm, 256, SMEMG>>>(
        p_hH, p_hL, DE, nullptr, nullptr, 0, KOFF_M1, nullptr,
        p_t, nullptr, nullptr, n);
    aggregate2<<<(n + 7) / 8, 256>>>(p_t, b_mp1, p_h2H, p_h2L, n);

    // heads: C = h@Wc, Ut = et@Wut, Uv = ev@Wuv
    long MO = (long)n * 40;
    gemm_heads<<<gmh, 256, SMEMH>>>(p_h2H, p_h2L, 0, b_c,  out + MO,     n);
    gemm_heads<<<gmh, 256, SMEMH>>>(p_etH, p_etL, 1, b_ut, out + 2 * MO, n);
    gemm_heads<<<gmh, 256, SMEMH>>>(p_evH, p_evL, 2, b_uv, out + 3 * MO, n);

    // final average (m4 = MO/4 float4 groups)
    long m4 = MO / 4;
    avg_kernel<<<(int)((m4 + 255) / 256), 256>>>(out, m4);
}